// round 9
// baseline (speedup 1.0000x reference)
#include <cuda_runtime.h>
#include <math.h>
#include <mma.h>

using namespace nvcuda;

#define BB 8
#define SS 2048
#define KIN 128
#define NIN 256
#define NPROC 1024
#define KPROC 256
#define DM 1024

// ---------------- scratch (device globals; no allocation allowed) ----------------
__device__ float g_PWT[NIN * NPROC];
__device__ float g_Wg[BB * KIN * NPROC];
__device__ float g_part[BB * 16 * NPROC];
__device__ int   g_pidx[BB * KPROC];
__device__ float g_actsT[(size_t)BB * NPROC * SS]; // gelu acts, transposed, tf32-rounded
__device__ float g_Ptf[NPROC * DM];                // process_outputs, tf32-rounded

__device__ __forceinline__ float gelu_exact(float x) {
    return 0.5f * x * (1.0f + erff(x * 0.70710678118654752f));
}

// ---------------- K0: transpose process_weights [1024][256] -> PWT [256][1024] ----
__global__ void k_transpose(const float* __restrict__ pw) {
    __shared__ float t[32][33];
    int x = blockIdx.x * 32 + threadIdx.x;
    int y = blockIdx.y * 32 + threadIdx.y;
    #pragma unroll
    for (int i = 0; i < 32; i += 8)
        t[threadIdx.y + i][threadIdx.x] = pw[(y + i) * NIN + x];
    __syncthreads();
    int x2 = blockIdx.y * 32 + threadIdx.x;
    int y2 = blockIdx.x * 32 + threadIdx.y;
    #pragma unroll
    for (int i = 0; i < 32; i += 8)
        g_PWT[(y2 + i) * NPROC + x2] = t[threadIdx.x][threadIdx.y + i];
}

// ---------------- K1: gather Wg[b][k][:] = PWT[input_idx[b][k]][:] -----------------
__global__ void k_gather_wg(const int* __restrict__ iidx) {
    int b = blockIdx.x / KIN;
    int k = blockIdx.x % KIN;
    int c = iidx[b * KIN + k];
    const float4* src = (const float4*)&g_PWT[(size_t)c * NPROC];
    float4* dst = (float4*)&g_Wg[((size_t)b * KIN + k) * NPROC];
    dst[threadIdx.x] = src[threadIdx.x];
}

// ---------------- K1b: pre-round process_outputs to tf32 bit patterns --------------
__global__ void k_round_P(const float* __restrict__ P) {
    int idx = blockIdx.x * blockDim.x + threadIdx.x;
    float4 v = ((const float4*)P)[idx];
    v.x = wmma::__float_to_tf32(v.x); v.y = wmma::__float_to_tf32(v.y);
    v.z = wmma::__float_to_tf32(v.z); v.w = wmma::__float_to_tf32(v.w);
    ((float4*)g_Ptf)[idx] = v;
}

// ---------------- K2: scores via 3xTF32 TC GEMM + exact-fp32 gelu/colsum epilogue --
// grid (16 m, 8 n, 8 b), 128 threads = 4 warps (2x2), warp tile 64x64.
// A (X) row_major [m][k], B (Wg) row_major [k][n]; split-precision hi/lo,
// products hi*hi + hi*lo + lo*hi (error ~1e-6 rel << 1e-3 order-stat gaps).
#define K2_A_PITCH 36
#define K2_B_PITCH 136
#define K2_STAGE_F (128 * K2_A_PITCH + 32 * K2_B_PITCH)   // 8960 floats
#define K2_EPS_PITCH 132

__device__ __forceinline__ void k2_issue_stage(float* dsm, int s, int kc,
                                               const float* Xb, const float* Bm,
                                               int m0, int n0, int tid) {
    float* As_ = dsm + s * K2_STAGE_F;
    float* Bs_ = As_ + 128 * K2_A_PITCH;
    #pragma unroll
    for (int it = 0; it < 8; it++) {
        int idx = tid + it * 128;
        int row = idx >> 3, c4 = (idx & 7) * 4;
        unsigned dst = (unsigned)__cvta_generic_to_shared(&As_[row * K2_A_PITCH + c4]);
        const float* src = &Xb[(m0 + row) * KIN + kc + c4];
        asm volatile("cp.async.cg.shared.global [%0], [%1], 16;\n" :: "r"(dst), "l"(src));
    }
    #pragma unroll
    for (int it = 0; it < 8; it++) {
        int idx = tid + it * 128;
        int row = idx >> 5, c4 = (idx & 31) * 4;
        unsigned dst = (unsigned)__cvta_generic_to_shared(&Bs_[row * K2_B_PITCH + c4]);
        const float* src = &Bm[(kc + row) * NPROC + n0 + c4];
        asm volatile("cp.async.cg.shared.global [%0], [%1], 16;\n" :: "r"(dst), "l"(src));
    }
    asm volatile("cp.async.commit_group;\n" ::);
}

__global__ __launch_bounds__(128) void k_scores_tc(const float* __restrict__ X) {
    extern __shared__ float dsm[];
    int b = blockIdx.z;
    int m0 = blockIdx.x * 128;
    int n0 = blockIdx.y * 128;
    int tid = threadIdx.x;
    int wid = tid >> 5;
    int wm = wid & 1;
    int wn = wid >> 1;
    const float* Xb = X + (size_t)b * SS * KIN;
    const float* Bm = g_Wg + (size_t)b * KIN * NPROC;

    wmma::fragment<wmma::accumulator, 16, 16, 8, float> acc[4][4];
    #pragma unroll
    for (int i = 0; i < 4; i++)
        #pragma unroll
        for (int j = 0; j < 4; j++) wmma::fill_fragment(acc[i][j], 0.0f);

    k2_issue_stage(dsm, 0, 0, Xb, Bm, m0, n0, tid);
    k2_issue_stage(dsm, 1, 32, Xb, Bm, m0, n0, tid);

    #pragma unroll
    for (int t = 0; t < 4; t++) {
        if (t < 3) asm volatile("cp.async.wait_group 1;\n" ::);
        else       asm volatile("cp.async.wait_group 0;\n" ::);
        __syncthreads();
        int s = t & 1;
        float* As_ = dsm + s * K2_STAGE_F;
        float* Bs_ = As_ + 128 * K2_A_PITCH;
        #pragma unroll
        for (int ks = 0; ks < 4; ks++) {
            wmma::fragment<wmma::matrix_b, 16, 16, 8, wmma::precision::tf32,
                           wmma::row_major> bhi[4], blo[4];
            #pragma unroll
            for (int j = 0; j < 4; j++) {
                wmma::load_matrix_sync(bhi[j], &Bs_[(ks * 8) * K2_B_PITCH + wn * 64 + j * 16],
                                       K2_B_PITCH);
                #pragma unroll
                for (int e = 0; e < bhi[j].num_elements; e++) {
                    float v = bhi[j].x[e];
                    float h = wmma::__float_to_tf32(v);
                    bhi[j].x[e] = h;
                    blo[j].x[e] = wmma::__float_to_tf32(v - h);
                }
            }
            #pragma unroll
            for (int i = 0; i < 4; i++) {
                wmma::fragment<wmma::matrix_a, 16, 16, 8, wmma::precision::tf32,
                               wmma::row_major> ahi, alo;
                wmma::load_matrix_sync(ahi, &As_[(wm * 64 + i * 16) * K2_A_PITCH + ks * 8],
                                       K2_A_PITCH);
                #pragma unroll
                for (int e = 0; e < ahi.num_elements; e++) {
                    float v = ahi.x[e];
                    float h = wmma::__float_to_tf32(v);
                    ahi.x[e] = h;
                    alo.x[e] = wmma::__float_to_tf32(v - h);
                }
                #pragma unroll
                for (int j = 0; j < 4; j++) {
                    wmma::mma_sync(acc[i][j], alo, bhi[j], acc[i][j]);
                    wmma::mma_sync(acc[i][j], ahi, blo[j], acc[i][j]);
                    wmma::mma_sync(acc[i][j], ahi, bhi[j], acc[i][j]);
                }
            }
        }
        __syncthreads();
        if (t + 2 < 4)
            k2_issue_stage(dsm, s, (t + 2) * 32, Xb, Bm, m0, n0, tid);
    }

    // epilogue: park accumulators col-major in smem -> eps[n][m] (pitch 132)
    __syncthreads();
    float* eps = dsm;
    #pragma unroll
    for (int i = 0; i < 4; i++)
        #pragma unroll
        for (int j = 0; j < 4; j++)
            wmma::store_matrix_sync(&eps[(wn * 64 + j * 16) * K2_EPS_PITCH + wm * 64 + i * 16],
                                    acc[i][j], K2_EPS_PITCH, wmma::mem_col_major);
    __syncthreads();
    // thread n: exact gelu, sequential column sum (deterministic), tf32 acts out
    {
        int n = tid;
        const float* src = &eps[n * K2_EPS_PITCH];
        float* dst = &g_actsT[((size_t)b * NPROC + n0 + n) * SS + m0];
        float s = 0.f;
        #pragma unroll 8
        for (int c = 0; c < 32; c++) {
            float4 v = *(const float4*)&src[c * 4];
            float g0 = gelu_exact(v.x), g1 = gelu_exact(v.y);
            float g2 = gelu_exact(v.z), g3 = gelu_exact(v.w);
            s += g0; s += g1; s += g2; s += g3;
            *(float4*)&dst[c * 4] = make_float4(
                wmma::__float_to_tf32(g0), wmma::__float_to_tf32(g1),
                wmma::__float_to_tf32(g2), wmma::__float_to_tf32(g3));
        }
        g_part[((size_t)b * 16 + blockIdx.x) * NPROC + n0 + n] = s;
    }
}

// ---------------- K4: per-batch reduce + bitonic top-256 of 1024 -------------------
__global__ __launch_bounds__(512) void k_topk() {
    __shared__ float sv[NPROC];
    __shared__ int   si[NPROC];
    int b = blockIdx.x;
    int tid = threadIdx.x;
    for (int t = tid; t < NPROC; t += 512) {
        float s = 0.f;
        #pragma unroll
        for (int r = 0; r < 16; r++) s += g_part[((size_t)b * 16 + r) * NPROC + t];
        sv[t] = s; si[t] = t;
    }
    __syncthreads();
    for (int k = 2; k <= NPROC; k <<= 1) {
        for (int j = k >> 1; j > 0; j >>= 1) {
            int i = ((tid & ~(j - 1)) << 1) | (tid & (j - 1));
            int ixj = i | j;
            bool desc = ((i & k) == 0);
            float v1 = sv[i], v2 = sv[ixj];
            if ((v1 < v2) == desc) {
                sv[i] = v2; sv[ixj] = v1;
                int tmp = si[i]; si[i] = si[ixj]; si[ixj] = tmp;
            }
            __syncthreads();
        }
    }
    if (tid < KPROC) g_pidx[b * KPROC + tid] = si[tid];
}

// ---------------- K6: out = actsT_sel^T @ Ptf_sel — TF32 TC + cp.async pipeline ----
#define K6_STAGE_F 8704              // floats per stage: As 32*136 + Bs 32*136
__device__ __forceinline__ void k6_issue_stage(float* dsm, int s, int kc,
                                               const float* AT, const int* pidx,
                                               int m0, int n0, int tid) {
    float* As_ = dsm + s * K6_STAGE_F;
    float* Bs_ = As_ + 4352;
    #pragma unroll
    for (int it = 0; it < 8; it++) {
        int idx = tid + it * 128;
        int row = idx >> 5, c4 = (idx & 31) * 4;
        int nr = pidx[kc + row];
        unsigned dst = (unsigned)__cvta_generic_to_shared(&As_[row * 136 + c4]);
        const float* src = &AT[(size_t)nr * SS + m0 + c4];
        asm volatile("cp.async.cg.shared.global [%0], [%1], 16;\n" :: "r"(dst), "l"(src));
    }
    #pragma unroll
    for (int it = 0; it < 8; it++) {
        int idx = tid + it * 128;
        int row = idx >> 5, c4 = (idx & 31) * 4;
        int nr = pidx[kc + row];
        unsigned dst = (unsigned)__cvta_generic_to_shared(&Bs_[row * 136 + c4]);
        const float* src = &g_Ptf[(size_t)nr * DM + n0 + c4];
        asm volatile("cp.async.cg.shared.global [%0], [%1], 16;\n" :: "r"(dst), "l"(src));
    }
    asm volatile("cp.async.commit_group;\n" ::);
}

__global__ __launch_bounds__(128) void k_out_tc(float* __restrict__ out) {
    extern __shared__ float dsm[];
    int b = blockIdx.z;
    int m0 = blockIdx.x * 128;
    int n0 = blockIdx.y * 128;
    int tid = threadIdx.x;
    int wid = tid >> 5;
    int wm = wid & 1;
    int wn = wid >> 1;
    const float* AT = g_actsT + (size_t)b * NPROC * SS;
    const int* pidx = g_pidx + b * KPROC;

    wmma::fragment<wmma::accumulator, 16, 16, 8, float> acc[4][4];
    #pragma unroll
    for (int i = 0; i < 4; i++)
        #pragma unroll
        for (int j = 0; j < 4; j++) wmma::fill_fragment(acc[i][j], 0.0f);

    k6_issue_stage(dsm, 0, 0, AT, pidx, m0, n0, tid);
    k6_issue_stage(dsm, 1, 32, AT, pidx, m0, n0, tid);

    #pragma unroll
    for (int t = 0; t < 8; t++) {
        if (t < 7) asm volatile("cp.async.wait_group 1;\n" ::);
        else       asm volatile("cp.async.wait_group 0;\n" ::);
        __syncthreads();
        int s = t & 1;
        float* As_ = dsm + s * K6_STAGE_F;
        float* Bs_ = As_ + 4352;
        #pragma unroll
        for (int ks = 0; ks < 4; ks++) {
            wmma::fragment<wmma::matrix_a, 16, 16, 8, wmma::precision::tf32,
                           wmma::col_major> af[4];
            wmma::fragment<wmma::matrix_b, 16, 16, 8, wmma::precision::tf32,
                           wmma::row_major> bf[4];
            #pragma unroll
            for (int i = 0; i < 4; i++)
                wmma::load_matrix_sync(af[i], &As_[(ks * 8) * 136 + wm * 64 + i * 16], 136);
            #pragma unroll
            for (int j = 0; j < 4; j++)
                wmma::load_matrix_sync(bf[j], &Bs_[(ks * 8) * 136 + wn * 64 + j * 16], 136);
            #pragma unroll
            for (int i = 0; i < 4; i++)
                #pragma unroll
                for (int j = 0; j < 4; j++)
                    wmma::mma_sync(acc[i][j], af[i], bf[j], acc[i][j]);
        }
        __syncthreads();
        if (t + 2 < 8)
            k6_issue_stage(dsm, s, (t + 2) * 32, AT, pidx, m0, n0, tid);
    }
    #pragma unroll
    for (int i = 0; i < 4; i++)
        #pragma unroll
        for (int j = 0; j < 4; j++) {
            float* dst = out + ((size_t)(b * SS + m0 + wm * 64 + i * 16)) * DM
                             + n0 + wn * 64 + j * 16;
            wmma::store_matrix_sync(dst, acc[i][j], DM, wmma::mem_row_major);
        }
}

// ---------------- launch -----------------------------------------------------------
extern "C" void kernel_launch(void* const* d_in, const int* in_sizes, int n_in,
                              void* d_out, int out_size) {
    const float* X    = (const float*)d_in[0];   // [8,2048,128]
    const float* PW   = (const float*)d_in[1];   // [1024,256]
    const float* PO   = (const float*)d_in[2];   // [1024,1024]
    const int*   IIDX = (const int*)d_in[3];     // [8,128]

    cudaFuncSetAttribute(k_out_tc, cudaFuncAttributeMaxDynamicSharedMemorySize,
                         2 * K6_STAGE_F * 4);
    cudaFuncSetAttribute(k_scores_tc, cudaFuncAttributeMaxDynamicSharedMemorySize,
                         2 * K2_STAGE_F * 4);

    k_transpose<<<dim3(NIN / 32, NPROC / 32), dim3(32, 8)>>>(PW);
    k_gather_wg<<<BB * KIN, 256>>>(IIDX);
    k_round_P<<<(NPROC * DM / 4) / 256, 256>>>(PO);
    k_scores_tc<<<dim3(16, 8, BB), 128, 2 * K2_STAGE_F * 4>>>(X);
    k_topk<<<BB, 512>>>();
    k_out_tc<<<dim3(16, 8, BB), 128, 2 * K6_STAGE_F * 4>>>((float*)d_out);
}

// round 10
// speedup vs baseline: 1.2972x; 1.2972x over previous
#include <cuda_runtime.h>
#include <math.h>
#include <mma.h>

using namespace nvcuda;

#define BB 8
#define SS 2048
#define KIN 128
#define NIN 256
#define NPROC 1024
#define KPROC 256
#define DM 1024

// ---------------- scratch (device globals; no allocation allowed) ----------------
__device__ float g_PWT[NIN * NPROC];
__device__ float g_Wg[BB * KIN * NPROC];
__device__ float g_part[BB * 16 * NPROC];
__device__ int   g_pidx[BB * KPROC];
__device__ float g_actsT[(size_t)BB * NPROC * SS]; // gelu acts, transposed, tf32-rounded
__device__ float g_Ptf[NPROC * DM];                // process_outputs, tf32-rounded

__device__ __forceinline__ float gelu_exact(float x) {
    return 0.5f * x * (1.0f + erff(x * 0.70710678118654752f));
}

// ---------------- K0: transpose process_weights [1024][256] -> PWT [256][1024] ----
__global__ void k_transpose(const float* __restrict__ pw) {
    __shared__ float t[32][33];
    int x = blockIdx.x * 32 + threadIdx.x;
    int y = blockIdx.y * 32 + threadIdx.y;
    #pragma unroll
    for (int i = 0; i < 32; i += 8)
        t[threadIdx.y + i][threadIdx.x] = pw[(y + i) * NIN + x];
    __syncthreads();
    int x2 = blockIdx.y * 32 + threadIdx.x;
    int y2 = blockIdx.x * 32 + threadIdx.y;
    #pragma unroll
    for (int i = 0; i < 32; i += 8)
        g_PWT[(y2 + i) * NPROC + x2] = t[threadIdx.x][threadIdx.y + i];
}

// ---------------- K1: gather Wg[b][k][:] = PWT[input_idx[b][k]][:] -----------------
__global__ void k_gather_wg(const int* __restrict__ iidx) {
    int b = blockIdx.x / KIN;
    int k = blockIdx.x % KIN;
    int c = iidx[b * KIN + k];
    const float4* src = (const float4*)&g_PWT[(size_t)c * NPROC];
    float4* dst = (float4*)&g_Wg[((size_t)b * KIN + k) * NPROC];
    dst[threadIdx.x] = src[threadIdx.x];
}

// ---------------- K1b: pre-round process_outputs to tf32 bit patterns --------------
__global__ void k_round_P(const float* __restrict__ P) {
    int idx = blockIdx.x * blockDim.x + threadIdx.x;
    float4 v = ((const float4*)P)[idx];
    v.x = wmma::__float_to_tf32(v.x); v.y = wmma::__float_to_tf32(v.y);
    v.z = wmma::__float_to_tf32(v.z); v.w = wmma::__float_to_tf32(v.w);
    ((float4*)g_Ptf)[idx] = v;
}

// ---------------- K2: GEMM1 + gelu (SIMT fp32, R8 measured-good version) -----------
// 128x128 tile, 8x8 microtile, K-tile 32; scores bit-identical baseline.
__global__ __launch_bounds__(256) void k_scores(const float* __restrict__ X) {
    __shared__ float As[32][128];
    __shared__ float Bs[32][128];
    int b = blockIdx.z;
    int m0 = blockIdx.x * 128;
    int n0 = blockIdx.y * 128;
    int tid = threadIdx.x;
    int tx = tid & 15, ty = tid >> 4;
    const float* A = X + (size_t)b * SS * KIN;
    const float* Bm = g_Wg + (size_t)b * KIN * NPROC;
    float acc[8][8];
    #pragma unroll
    for (int i = 0; i < 8; i++)
        #pragma unroll
        for (int j = 0; j < 8; j++) acc[i][j] = 0.f;

    for (int kc = 0; kc < KIN; kc += 32) {
        #pragma unroll
        for (int it = 0; it < 4; it++) {
            int idx = tid + it * 256;
            int row = idx >> 3, c4 = (idx & 7) * 4;
            float4 v = *(const float4*)&A[(m0 + row) * KIN + kc + c4];
            As[c4 + 0][row] = v.x; As[c4 + 1][row] = v.y;
            As[c4 + 2][row] = v.z; As[c4 + 3][row] = v.w;
        }
        #pragma unroll
        for (int it = 0; it < 4; it++) {
            int idx = tid + it * 256;
            int row = idx >> 5, c4 = (idx & 31) * 4;
            *(float4*)&Bs[row][c4] =
                *(const float4*)&Bm[(kc + row) * NPROC + n0 + c4];
        }
        __syncthreads();
        #pragma unroll
        for (int kk = 0; kk < 32; kk++) {
            float a[8], bv[8];
            #pragma unroll
            for (int i = 0; i < 8; i++) a[i] = As[kk][ty * 8 + i];
            *(float4*)&bv[0] = *(const float4*)&Bs[kk][tx * 4];
            *(float4*)&bv[4] = *(const float4*)&Bs[kk][64 + tx * 4];
            #pragma unroll
            for (int i = 0; i < 8; i++)
                #pragma unroll
                for (int j = 0; j < 8; j++) acc[i][j] += a[i] * bv[j];
        }
        __syncthreads();
    }
    float cs[8];
    #pragma unroll
    for (int j = 0; j < 8; j++) {
        float gv[8];
        float s = 0.f;
        #pragma unroll
        for (int i = 0; i < 8; i++) { gv[i] = gelu_exact(acc[i][j]); s += gv[i]; }
        cs[j] = s;
        int ncol = (j < 4) ? (tx * 4 + j) : (64 + tx * 4 + (j - 4));
        int n = n0 + ncol;
        float* dst = &g_actsT[((size_t)b * NPROC + n) * SS + m0 + ty * 8];
        *(float4*)dst = make_float4(
            wmma::__float_to_tf32(gv[0]), wmma::__float_to_tf32(gv[1]),
            wmma::__float_to_tf32(gv[2]), wmma::__float_to_tf32(gv[3]));
        *(float4*)(dst + 4) = make_float4(
            wmma::__float_to_tf32(gv[4]), wmma::__float_to_tf32(gv[5]),
            wmma::__float_to_tf32(gv[6]), wmma::__float_to_tf32(gv[7]));
    }
    __syncthreads();
    #pragma unroll
    for (int j = 0; j < 8; j++) {
        int ncol = (j < 4) ? (tx * 4 + j) : (64 + tx * 4 + (j - 4));
        As[ty][ncol] = cs[j];
    }
    __syncthreads();
    if (tid < 128) {
        float s = 0.f;
        #pragma unroll
        for (int r = 0; r < 16; r++) s += As[r][tid];
        g_part[((size_t)b * 16 + blockIdx.x) * NPROC + n0 + tid] = s;
    }
}

// ---------------- K4: per-batch reduce + bitonic top-256 of 1024 -------------------
__global__ __launch_bounds__(512) void k_topk() {
    __shared__ float sv[NPROC];
    __shared__ int   si[NPROC];
    int b = blockIdx.x;
    int tid = threadIdx.x;
    for (int t = tid; t < NPROC; t += 512) {
        float s = 0.f;
        #pragma unroll
        for (int r = 0; r < 16; r++) s += g_part[((size_t)b * 16 + r) * NPROC + t];
        sv[t] = s; si[t] = t;
    }
    __syncthreads();
    for (int k = 2; k <= NPROC; k <<= 1) {
        for (int j = k >> 1; j > 0; j >>= 1) {
            int i = ((tid & ~(j - 1)) << 1) | (tid & (j - 1));
            int ixj = i | j;
            bool desc = ((i & k) == 0);
            float v1 = sv[i], v2 = sv[ixj];
            if ((v1 < v2) == desc) {
                sv[i] = v2; sv[ixj] = v1;
                int tmp = si[i]; si[i] = si[ixj]; si[ixj] = tmp;
            }
            __syncthreads();
        }
    }
    if (tid < KPROC) g_pidx[b * KPROC + tid] = si[tid];
}

// ---------------- K6: out = actsT_sel^T @ Ptf_sel — TF32 TC ------------------------
// Block tile M=128 x N=256, K-tile 32; 256 threads = 8 warps (2 wm x 4 wn),
// warp tile 64x64. 3-stage cp.async ring, ONE __syncthreads per stage.
#define K6_A_F  (32 * 136)           // 4352 floats
#define K6_B_F  (32 * 264)           // 8448 floats
#define K6_STAGE_F (K6_A_F + K6_B_F) // 12800 floats
#define K6_NT 8                      // 256 / 32 K-steps

__device__ __forceinline__ void k6_issue_stage(float* dsm, int s, int kc,
                                               const float* AT, const int* pidx,
                                               int m0, int n0, int tid) {
    float* As_ = dsm + s * K6_STAGE_F;
    float* Bs_ = As_ + K6_A_F;
    // A: 128 m x 32 k -> As[k][m], 1024 float4, 4 per thread
    #pragma unroll
    for (int it = 0; it < 4; it++) {
        int idx = tid + it * 256;
        int row = idx >> 5, c4 = (idx & 31) * 4;
        int nr = pidx[kc + row];
        unsigned dst = (unsigned)__cvta_generic_to_shared(&As_[row * 136 + c4]);
        const float* src = &AT[(size_t)nr * SS + m0 + c4];
        asm volatile("cp.async.cg.shared.global [%0], [%1], 16;\n" :: "r"(dst), "l"(src));
    }
    // B: 32 k x 256 n -> Bs[k][n], 2048 float4, 8 per thread
    #pragma unroll
    for (int it = 0; it < 8; it++) {
        int idx = tid + it * 256;
        int row = idx >> 6, c4 = (idx & 63) * 4;
        int nr = pidx[kc + row];
        unsigned dst = (unsigned)__cvta_generic_to_shared(&Bs_[row * 264 + c4]);
        const float* src = &g_Ptf[(size_t)nr * DM + n0 + c4];
        asm volatile("cp.async.cg.shared.global [%0], [%1], 16;\n" :: "r"(dst), "l"(src));
    }
    asm volatile("cp.async.commit_group;\n" ::);
}

__global__ __launch_bounds__(256) void k_out_tc(float* __restrict__ out) {
    extern __shared__ float dsm[];
    int b = blockIdx.z;
    int m0 = blockIdx.x * 128;
    int n0 = blockIdx.y * 256;
    int tid = threadIdx.x;
    int wid = tid >> 5;
    int wm = wid & 1;                 // 2 slabs of 64 rows
    int wn = wid >> 1;                // 4 slabs of 64 cols
    const float* AT = g_actsT + (size_t)b * NPROC * SS;
    const int* pidx = g_pidx + b * KPROC;

    wmma::fragment<wmma::accumulator, 16, 16, 8, float> acc[4][4];
    #pragma unroll
    for (int i = 0; i < 4; i++)
        #pragma unroll
        for (int j = 0; j < 4; j++) wmma::fill_fragment(acc[i][j], 0.0f);

    k6_issue_stage(dsm, 0, 0, AT, pidx, m0, n0, tid);
    k6_issue_stage(dsm, 1, 32, AT, pidx, m0, n0, tid);

    #pragma unroll
    for (int t = 0; t < K6_NT; t++) {
        // wait for stage t: outstanding groups {t, t+1} (t+2 not yet issued)
        if (t < K6_NT - 1) asm volatile("cp.async.wait_group 1;\n" ::);
        else               asm volatile("cp.async.wait_group 0;\n" ::);
        __syncthreads();   // stage t visible; all warps done computing t-1
        if (t + 2 < K6_NT)
            k6_issue_stage(dsm, (t + 2) % 3, (t + 2) * 32, AT, pidx, m0, n0, tid);
        float* As_ = dsm + (t % 3) * K6_STAGE_F;
        float* Bs_ = As_ + K6_A_F;
        #pragma unroll
        for (int ks = 0; ks < 4; ks++) {
            wmma::fragment<wmma::matrix_a, 16, 16, 8, wmma::precision::tf32,
                           wmma::col_major> af[4];
            wmma::fragment<wmma::matrix_b, 16, 16, 8, wmma::precision::tf32,
                           wmma::row_major> bf[4];
            #pragma unroll
            for (int i = 0; i < 4; i++)
                wmma::load_matrix_sync(af[i], &As_[(ks * 8) * 136 + wm * 64 + i * 16], 136);
            #pragma unroll
            for (int j = 0; j < 4; j++)
                wmma::load_matrix_sync(bf[j], &Bs_[(ks * 8) * 264 + wn * 64 + j * 16], 264);
            #pragma unroll
            for (int i = 0; i < 4; i++)
                #pragma unroll
                for (int j = 0; j < 4; j++)
                    wmma::mma_sync(acc[i][j], af[i], bf[j], acc[i][j]);
        }
    }
    #pragma unroll
    for (int i = 0; i < 4; i++)
        #pragma unroll
        for (int j = 0; j < 4; j++) {
            float* dst = out + ((size_t)(b * SS + m0 + wm * 64 + i * 16)) * DM
                             + n0 + wn * 64 + j * 16;
            wmma::store_matrix_sync(dst, acc[i][j], DM, wmma::mem_row_major);
        }
}

// ---------------- launch -----------------------------------------------------------
extern "C" void kernel_launch(void* const* d_in, const int* in_sizes, int n_in,
                              void* d_out, int out_size) {
    const float* X    = (const float*)d_in[0];   // [8,2048,128]
    const float* PW   = (const float*)d_in[1];   // [1024,256]
    const float* PO   = (const float*)d_in[2];   // [1024,1024]
    const int*   IIDX = (const int*)d_in[3];     // [8,128]

    cudaFuncSetAttribute(k_out_tc, cudaFuncAttributeMaxDynamicSharedMemorySize,
                         3 * K6_STAGE_F * 4);

    k_transpose<<<dim3(NIN / 32, NPROC / 32), dim3(32, 8)>>>(PW);
    k_gather_wg<<<BB * KIN, 256>>>(IIDX);
    k_round_P<<<(NPROC * DM / 4) / 256, 256>>>(PO);
    k_scores<<<dim3(16, 8, BB), 256>>>(X);
    k_topk<<<BB, 512>>>();
    k_out_tc<<<dim3(16, 4, BB), 256, 3 * K6_STAGE_F * 4>>>((float*)d_out);
}